// round 5
// baseline (speedup 1.0000x reference)
#include <cuda_runtime.h>
#include <cuda_bf16.h>

#define N_SERIES 2048
#define N_TIME   4096
#define INPUT_SIZE 28
#define OUTPUT_SIZE 7
#define SEAS 7
#define EMB  9
#define S_LEN (N_TIME + SEAS)   /* 4103 */

#define OFF_YHAT 0
#define OFF_YWIN 401408
#define OFF_LEV  501760
#define OFF_SEAS (501760 + N_SERIES * N_TIME)

/* 13 chunks x 315 steps. Pass A: 189-step warmup from phase-aligned guess +
   315-step body (state only). Pass B: body from handoff, measures gauge
   ratio. Pass C: body with gauge-corrected init, stores L,S (+ fused
   windows output from chunk 12, ywin zeros from chunk 0). */
#define NCHUNK 13
#define BODY 315
#define TS   63

__device__ float g_lev [NCHUNK][N_SERIES];
__device__ float g_ring[NCHUNK][SEAS][N_SERIES];
__device__ float g_e   [NCHUNK][N_SERIES];
__device__ float g_gam [NCHUNK][N_SERIES];

__device__ __forceinline__ float frcp(float x) {
    float r;
    asm("rcp.approx.f32 %0, %1;" : "=f"(r) : "f"(x));
    return r;
}

__device__ __forceinline__ void load_params(const int* idxs, const float* emb,
                                            int s, float& a, float& oma,
                                            float& b, float& omb, float* is)
{
    const float* ew = emb + (size_t)idxs[s] * EMB;
    a = 1.0f / (1.0f + __expf(-ew[0]));
    b = 1.0f / (1.0f + __expf(-ew[1]));
    oma = 1.0f - a;
    omb = 1.0f - b;
#pragma unroll
    for (int k = 0; k < SEAS; k++) is[k] = __expf(ew[2 + k]);
}

__device__ __forceinline__ void load_tile(float (*ty)[33], const float* y,
                                          int sg, int tstart, int lane)
{
#pragma unroll 8
    for (int r = 0; r < 32; r++) {
        const float* row = y + (size_t)(sg * 32 + r) * N_TIME + tstart;
        ty[lane][r] = __ldg(row + lane);
        if (lane + 32 < TS) ty[lane + 32][r] = __ldg(row + lane + 32);
    }
}

/* Period-batched scan: all 7 ring/qring slots consumed in period g are final
   at period start, so the 7 loads + 7 a*yt*q products are independent; the
   lev FMA chain is the only serial dependency; rlev/ns/rcp(ns) dangle off
   it with 7 steps of slack before consumption. */
template<bool STORE>
__device__ __forceinline__ void scan_tile(const float (*ty)[33],
                                          float (*tl)[33], float (*ts)[33],
                                          int lane, float a, float oma,
                                          float b, float omb,
                                          float& lev, float* ring, float* qring)
{
#pragma unroll
    for (int g = 0; g < TS / SEAS; g++) {
        float yt[SEAS], ax[SEAS];
#pragma unroll
        for (int j = 0; j < SEAS; j++) yt[j] = ty[g * SEAS + j][lane];
#pragma unroll
        for (int j = 0; j < SEAS; j++) ax[j] = a * (yt[j] * qring[j]);
#pragma unroll
        for (int j = 0; j < SEAS; j++) {
            lev = fmaf(oma, lev, ax[j]);
            if (STORE) tl[g * SEAS + j][lane] = lev;
            float ns = fmaf(omb, ring[j], __fdividef(b * yt[j], lev));
            if (STORE) ts[g * SEAS + j][lane] = ns;
            ring[j]  = ns;
            qring[j] = frcp(ns);
        }
    }
}

/* ---- Pass A: warmup + body, state only ---- */
__global__ void __launch_bounds__(32)
passA_kernel(const float* __restrict__ y, const int* __restrict__ idxs,
             const float* __restrict__ emb)
{
    __shared__ float ty[TS][33];
    const int c    = blockIdx.x / 64;
    const int sg   = blockIdx.x % 64;
    const int lane = threadIdx.x;
    const int s    = sg * 32 + lane;

    float a, oma, b, omb, is[SEAS];
    load_params(idxs, emb, s, a, oma, b, omb, is);

    const int t0     = (c == 0) ? 1 : (c * BODY - 188);
    const int ntiles = (c == 0) ? 5 : 8;

    float lev = __fdividef(__ldg(y + (size_t)s * N_TIME + (t0 - 1)), is[0]);
    float ring[SEAS] = { is[1], is[2], is[3], is[4], is[5], is[6], is[0] };
    float qring[SEAS];
#pragma unroll
    for (int j = 0; j < SEAS; j++) qring[j] = frcp(ring[j]);

    for (int tile = 0; tile < ntiles; tile++) {
        load_tile(ty, y, sg, t0 + tile * TS, lane);
        __syncwarp();
        scan_tile<false>(ty, 0, 0, lane, a, oma, b, omb, lev, ring, qring);
        __syncwarp();
    }
    g_lev[c][s] = lev;
#pragma unroll
    for (int j = 0; j < SEAS; j++) g_ring[c][j][s] = ring[j];
}

/* ---- Pass B: body from handoff, emit end level ---- */
__global__ void __launch_bounds__(32)
passB_kernel(const float* __restrict__ y, const int* __restrict__ idxs,
             const float* __restrict__ emb)
{
    __shared__ float ty[TS][33];
    const int c    = blockIdx.x / 64 + 1;
    const int sg   = blockIdx.x % 64;
    const int lane = threadIdx.x;
    const int s    = sg * 32 + lane;

    float a, oma, b, omb, is[SEAS];
    load_params(idxs, emb, s, a, oma, b, omb, is);

    float lev = g_lev[c - 1][s];
    float ring[SEAS], qring[SEAS];
#pragma unroll
    for (int j = 0; j < SEAS; j++) {
        ring[j]  = g_ring[c - 1][j][s];
        qring[j] = frcp(ring[j]);
    }

    const int t0 = c * BODY + 1;
    for (int tile = 0; tile < 5; tile++) {
        load_tile(ty, y, sg, t0 + tile * TS, lane);
        __syncwarp();
        scan_tile<false>(ty, 0, 0, lane, a, oma, b, omb, lev, ring, qring);
        __syncwarp();
    }
    g_e[c][s] = lev;
}

/* ---- gauge chain ---- */
__global__ void fixup_kernel()
{
    int s = blockIdx.x * blockDim.x + threadIdx.x;
    if (s >= N_SERIES) return;
    g_gam[0][s] = 1.0f;
    g_gam[1][s] = 1.0f;
    float kap = 1.0f;
    for (int c = 1; c < NCHUNK - 1; c++) {
        kap *= g_lev[c][s] / g_e[c][s];
        g_gam[c + 1][s] = kap;
    }
}

/* ---- Pass C: body, gauge-corrected, stores L,S; fused windows ---- */
__global__ void __launch_bounds__(32)
passC_kernel(const float* __restrict__ y, const int* __restrict__ idxs,
             const float* __restrict__ emb,
             float* __restrict__ L, float* __restrict__ S,
             float* __restrict__ yhat, float* __restrict__ ywin)
{
    __shared__ float ty[TS][33];
    __shared__ float tl[TS][33];
    __shared__ float ts[TS][33];
    const int c    = blockIdx.x / 64;
    const int sg   = blockIdx.x % 64;
    const int lane = threadIdx.x;
    const int s    = sg * 32 + lane;

    float a, oma, b, omb, is[SEAS];
    load_params(idxs, emb, s, a, oma, b, omb, is);

    float lev, ring[SEAS], qring[SEAS];
    if (c == 0) {
        lev = __fdividef(__ldg(y + (size_t)s * N_TIME), is[0]);
        ring[0] = is[1]; ring[1] = is[2]; ring[2] = is[3];
        ring[3] = is[4]; ring[4] = is[5]; ring[5] = is[6]; ring[6] = is[0];
        float* Sr = S + (size_t)s * S_LEN;
#pragma unroll
        for (int k = 0; k < SEAS; k++) Sr[k] = is[k];
        Sr[SEAS] = is[0];
        L[(size_t)s * N_TIME] = lev;
        /* ywin zeros: [7][2048][7] */
#pragma unroll
        for (int w = 0; w < OUTPUT_SIZE; w++)
#pragma unroll
            for (int o = 0; o < OUTPUT_SIZE; o++)
                ywin[((w * N_SERIES) + s) * OUTPUT_SIZE + o] = 0.0f;
    } else {
        float gam  = g_gam[c][s];
        float igam = 1.0f / gam;
        lev = g_lev[c - 1][s] * igam;
#pragma unroll
        for (int j = 0; j < SEAS; j++) ring[j] = g_ring[c - 1][j][s] * gam;
    }
#pragma unroll
    for (int j = 0; j < SEAS; j++) qring[j] = frcp(ring[j]);

    const int t0  = c * BODY + 1;
    const int to0 = lane, to1 = lane + 32;

    for (int tile = 0; tile < 5; tile++) {
        const int tstart = t0 + tile * TS;
        load_tile(ty, y, sg, tstart, lane);
        __syncwarp();
        scan_tile<true>(ty, tl, ts, lane, a, oma, b, omb, lev, ring, qring);
        __syncwarp();

        /* fused windows: chunk 12 tile 4 covers t in [4033, 4095] */
        if (c == NCHUNK - 1 && tile == 4) {
#pragma unroll
            for (int w = 0; w < OUTPUT_SIZE; w++) {
                float lv = tl[56 + w][lane];   /* L at t = 4089+w */
                for (int ii = 0; ii < INPUT_SIZE; ii++) {
                    int t = 4062 + w + ii;
                    float yy = ty[t - 4033][lane];
                    float se = ts[t - 4040][lane];
                    yhat[((w * N_SERIES) + s) * INPUT_SIZE + ii] =
                        logf(yy / (lv * se));
                }
            }
        }

#pragma unroll 8
        for (int r = 0; r < 32; r++) {
            const size_t lb = (size_t)(sg * 32 + r) * N_TIME + tstart;
            const size_t sb = (size_t)(sg * 32 + r) * S_LEN + tstart + SEAS;
            L[lb + to0] = tl[to0][r];
            S[sb + to0] = ts[to0][r];
            if (to1 < TS) {
                L[lb + to1] = tl[to1][r];
                S[sb + to1] = ts[to1][r];
            }
        }
        __syncwarp();
    }
}

extern "C" void kernel_launch(void* const* d_in, const int* in_sizes, int n_in,
                              void* d_out, int out_size) {
    const float* y    = (const float*)d_in[0];
    const int*   idxs = (const int*)  d_in[1];
    const float* emb  = (const float*)d_in[2];

    float* out  = (float*)d_out;
    float* yhat = out + OFF_YHAT;
    float* ywin = out + OFF_YWIN;
    float* L    = out + OFF_LEV;
    float* S    = out + OFF_SEAS;

    passA_kernel<<<NCHUNK * 64, 32>>>(y, idxs, emb);
    passB_kernel<<<(NCHUNK - 2) * 64, 32>>>(y, idxs, emb);
    fixup_kernel<<<(N_SERIES + 255) / 256, 256>>>();
    passC_kernel<<<NCHUNK * 64, 32>>>(y, idxs, emb, L, S, yhat, ywin);
}

// round 6
// speedup vs baseline: 1.0177x; 1.0177x over previous
#include <cuda_runtime.h>
#include <cuda_bf16.h>

#define N_SERIES 2048
#define N_TIME   4096
#define INPUT_SIZE 28
#define OUTPUT_SIZE 7
#define SEAS 7
#define EMB  9
#define S_LEN (N_TIME + SEAS)   /* 4103 */

#define OFF_YHAT 0
#define OFF_YWIN 401408
#define OFF_LEV  501760
#define OFF_SEAS (501760 + N_SERIES * N_TIME)

/* 39 chunks x 105 steps. Chunks 0..3 exact from t=1. Chunks >=4: passA runs
   350-step warmup from phase-aligned guess + 105-step body (455 = 13 tiles
   of 35). Non-gauge handoff error ~ 0.3*0.857^65 ~ 1.3e-5 (rate measured
   R3/R4); gauge mode removed exactly by the passB/fixup chain. */
#define NCHUNK 39
#define BODY 105
#define WARM 350
#define TS   35

__device__ float g_lev [NCHUNK][N_SERIES];
__device__ float g_ring[NCHUNK][SEAS][N_SERIES];
__device__ float g_e   [NCHUNK][N_SERIES];
__device__ float g_gam [NCHUNK][N_SERIES];

__device__ __forceinline__ float frcp(float x) {
    float r;
    asm("rcp.approx.f32 %0, %1;" : "=f"(r) : "f"(x));
    return r;
}

__device__ __forceinline__ void load_params(const int* idxs, const float* emb,
                                            int s, float& a, float& oma,
                                            float& b, float& omb, float* is)
{
    const float* ew = emb + (size_t)idxs[s] * EMB;
    a = 1.0f / (1.0f + __expf(-ew[0]));
    b = 1.0f / (1.0f + __expf(-ew[1]));
    oma = 1.0f - a;
    omb = 1.0f - b;
#pragma unroll
    for (int k = 0; k < SEAS; k++) is[k] = __expf(ew[2 + k]);
}

__device__ __forceinline__ void load_tile(float (*ty)[33], const float* y,
                                          int sg, int tstart, int lane)
{
#pragma unroll 8
    for (int r = 0; r < 32; r++) {
        const float* row = y + (size_t)(sg * 32 + r) * N_TIME + tstart;
        ty[lane][r] = __ldg(row + lane);
        if (lane < TS - 32) ty[lane + 32][r] = __ldg(row + lane + 32);
    }
}

/* Period-batched scan of one 35-step tile (5 periods). When STORE, the level
   is written back into the consumed y slot (ty doubles as the L tile). */
template<bool STORE>
__device__ __forceinline__ void scan_tile(float (*ty)[33], float (*ts)[33],
                                          int lane, float a, float oma,
                                          float b, float omb,
                                          float& lev, float* ring, float* qring)
{
#pragma unroll
    for (int g = 0; g < TS / SEAS; g++) {
        float yt[SEAS], ax[SEAS];
#pragma unroll
        for (int j = 0; j < SEAS; j++) yt[j] = ty[g * SEAS + j][lane];
#pragma unroll
        for (int j = 0; j < SEAS; j++) ax[j] = a * (yt[j] * qring[j]);
#pragma unroll
        for (int j = 0; j < SEAS; j++) {
            lev = fmaf(oma, lev, ax[j]);
            if (STORE) ty[g * SEAS + j][lane] = lev;
            float ns = fmaf(omb, ring[j], (b * yt[j]) * frcp(lev));
            if (STORE) ts[g * SEAS + j][lane] = ns;
            ring[j]  = ns;
            qring[j] = frcp(ns);
        }
    }
}

/* ---- Pass A: (warmup +) body, state only ---- */
__global__ void __launch_bounds__(32)
passA_kernel(const float* __restrict__ y, const int* __restrict__ idxs,
             const float* __restrict__ emb)
{
    __shared__ float ty[TS][33];
    const int c    = blockIdx.x / 64;
    const int sg   = blockIdx.x % 64;
    const int lane = threadIdx.x;
    const int s    = sg * 32 + lane;

    float a, oma, b, omb, is[SEAS];
    load_params(idxs, emb, s, a, oma, b, omb, is);

    /* c<4: exact init at t0=1, tiles=3(c+1). c>=4: guess at t0=105c-349
       (t0 == 1 mod 7 and mod 35), 13 tiles. */
    const int t0     = (c < 4) ? 1 : (c * BODY - (WARM - 1));
    const int ntiles = (c < 4) ? 3 * (c + 1) : 13;

    float lev = __fdividef(__ldg(y + (size_t)s * N_TIME + (t0 - 1)), is[0]);
    float ring[SEAS] = { is[1], is[2], is[3], is[4], is[5], is[6], is[0] };
    float qring[SEAS];
#pragma unroll
    for (int j = 0; j < SEAS; j++) qring[j] = frcp(ring[j]);

    for (int tile = 0; tile < ntiles; tile++) {
        load_tile(ty, y, sg, t0 + tile * TS, lane);
        __syncwarp();
        scan_tile<false>(ty, 0, lane, a, oma, b, omb, lev, ring, qring);
        __syncwarp();
    }
    g_lev[c][s] = lev;
#pragma unroll
    for (int j = 0; j < SEAS; j++) g_ring[c][j][s] = ring[j];
}

/* ---- Pass B: body from raw handoff, emit end level (chunks 4..37) ---- */
__global__ void __launch_bounds__(32)
passB_kernel(const float* __restrict__ y, const int* __restrict__ idxs,
             const float* __restrict__ emb)
{
    __shared__ float ty[TS][33];
    const int c    = blockIdx.x / 64 + 4;
    const int sg   = blockIdx.x % 64;
    const int lane = threadIdx.x;
    const int s    = sg * 32 + lane;

    float a, oma, b, omb, is[SEAS];
    load_params(idxs, emb, s, a, oma, b, omb, is);

    float lev = g_lev[c - 1][s];
    float ring[SEAS], qring[SEAS];
#pragma unroll
    for (int j = 0; j < SEAS; j++) {
        ring[j]  = g_ring[c - 1][j][s];
        qring[j] = frcp(ring[j]);
    }

    const int t0 = c * BODY + 1;
    for (int tile = 0; tile < 3; tile++) {
        load_tile(ty, y, sg, t0 + tile * TS, lane);
        __syncwarp();
        scan_tile<false>(ty, 0, lane, a, oma, b, omb, lev, ring, qring);
        __syncwarp();
    }
    g_e[c][s] = lev;
}

/* ---- gauge chain: kappa_c = kappa_{c-1} * A_c.lev / e_c; gamma_c = kappa_{c-1} ---- */
__global__ void fixup_kernel()
{
    int s = blockIdx.x * blockDim.x + threadIdx.x;
    if (s >= N_SERIES) return;
#pragma unroll
    for (int c = 0; c <= 4; c++) g_gam[c][s] = 1.0f;
    float kap = 1.0f;
    for (int c = 4; c < NCHUNK - 1; c++) {
        kap *= g_lev[c][s] / g_e[c][s];
        g_gam[c + 1][s] = kap;
    }
}

/* ---- Pass C: body with gauge-corrected init; stores L and S ---- */
__global__ void __launch_bounds__(32)
passC_kernel(const float* __restrict__ y, const int* __restrict__ idxs,
             const float* __restrict__ emb,
             float* __restrict__ L, float* __restrict__ S)
{
    __shared__ float ty[TS][33];   /* y tile; becomes L tile during scan */
    __shared__ float ts[TS][33];
    const int c    = blockIdx.x / 64;
    const int sg   = blockIdx.x % 64;
    const int lane = threadIdx.x;
    const int s    = sg * 32 + lane;

    float a, oma, b, omb, is[SEAS];
    load_params(idxs, emb, s, a, oma, b, omb, is);

    float lev, ring[SEAS], qring[SEAS];
    if (c == 0) {
        lev = __fdividef(__ldg(y + (size_t)s * N_TIME), is[0]);
        ring[0] = is[1]; ring[1] = is[2]; ring[2] = is[3];
        ring[3] = is[4]; ring[4] = is[5]; ring[5] = is[6]; ring[6] = is[0];
        float* Sr = S + (size_t)s * S_LEN;
#pragma unroll
        for (int k = 0; k < SEAS; k++) Sr[k] = is[k];
        Sr[SEAS] = is[0];
        L[(size_t)s * N_TIME] = lev;
    } else {
        float gam = g_gam[c][s];
        lev = g_lev[c - 1][s] * frcp(gam);
#pragma unroll
        for (int j = 0; j < SEAS; j++) ring[j] = g_ring[c - 1][j][s] * gam;
    }
#pragma unroll
    for (int j = 0; j < SEAS; j++) qring[j] = frcp(ring[j]);

    const int t0 = c * BODY + 1;

    for (int tile = 0; tile < 3; tile++) {
        const int tstart = t0 + tile * TS;
        load_tile(ty, y, sg, tstart, lane);
        __syncwarp();
        scan_tile<true>(ty, ts, lane, a, oma, b, omb, lev, ring, qring);
        __syncwarp();
#pragma unroll 8
        for (int r = 0; r < 32; r++) {
            const size_t lb = (size_t)(sg * 32 + r) * N_TIME + tstart;
            const size_t sb = (size_t)(sg * 32 + r) * S_LEN + tstart + SEAS;
            L[lb + lane] = ty[lane][r];
            S[sb + lane] = ts[lane][r];
            if (lane < TS - 32) {
                L[lb + lane + 32] = ty[lane + 32][r];
                S[sb + lane + 32] = ts[lane + 32][r];
            }
        }
        __syncwarp();
    }
}

__global__ void windows_kernel(const float* __restrict__ y,
                               const float* __restrict__ L,
                               const float* __restrict__ S,
                               float* __restrict__ yhat,
                               float* __restrict__ ywin)
{
    const int NH = OUTPUT_SIZE * N_SERIES * INPUT_SIZE;   /* 401408 */
    const int NZ = OUTPUT_SIZE * N_SERIES * OUTPUT_SIZE;  /* 100352 */
    int i = blockIdx.x * blockDim.x + threadIdx.x;
    if (i < NH) {
        int ii   = i % INPUT_SIZE;
        int rest = i / INPUT_SIZE;
        int s    = rest % N_SERIES;
        int w    = rest / N_SERIES;
        int start = N_TIME - INPUT_SIZE - OUTPUT_SIZE + 1 + w;
        int t = start + ii;
        float lev = L[(size_t)s * N_TIME + (start + INPUT_SIZE - 1)];
        float se  = S[(size_t)s * S_LEN  + t];
        float yy  = y[(size_t)s * N_TIME + t];
        yhat[i] = logf(yy / (lev * se));
    } else if (i < NH + NZ) {
        ywin[i - NH] = 0.0f;
    }
}

extern "C" void kernel_launch(void* const* d_in, const int* in_sizes, int n_in,
                              void* d_out, int out_size) {
    const float* y    = (const float*)d_in[0];
    const int*   idxs = (const int*)  d_in[1];
    const float* emb  = (const float*)d_in[2];

    float* out  = (float*)d_out;
    float* yhat = out + OFF_YHAT;
    float* ywin = out + OFF_YWIN;
    float* L    = out + OFF_LEV;
    float* S    = out + OFF_SEAS;

    passA_kernel<<<NCHUNK * 64, 32>>>(y, idxs, emb);
    passB_kernel<<<(NCHUNK - 5) * 64, 32>>>(y, idxs, emb);
    fixup_kernel<<<(N_SERIES + 255) / 256, 256>>>();
    passC_kernel<<<NCHUNK * 64, 32>>>(y, idxs, emb, L, S);

    const int tot = OUTPUT_SIZE * N_SERIES * (INPUT_SIZE + OUTPUT_SIZE); /* 501760 */
    windows_kernel<<<(tot + 255) / 256, 256>>>(y, L, S, yhat, ywin);
}

// round 7
// speedup vs baseline: 1.3497x; 1.3263x over previous
#include <cuda_runtime.h>
#include <cuda_bf16.h>
#include <cstdint>

#define N_SERIES 2048
#define N_TIME   4096
#define INPUT_SIZE 28
#define OUTPUT_SIZE 7
#define SEAS 7
#define EMB  9
#define S_LEN (N_TIME + SEAS)   /* 4103 */

#define OFF_YHAT 0
#define OFF_YWIN 401408
#define OFF_LEV  501760
#define OFF_SEAS (501760 + N_SERIES * N_TIME)

/* Relay scheme:
   passA: 39 relay chunks, BODY1=105, WARM=315 (45 periods; per-link error
   ~7.5e-5 by the HW-measured 0.81/period contraction). Chunks 0..3 are exact
   (t0 clamps to 1). Records fine states (lev+ring) every 35 steps -> 117 fine
   boundaries, plus each chunk's end level for the gauge chain.
   fixup: kappa_c = kappa_{c-1} * flev[3c]/endlev[c-1]  (exact gauge removal).
   passC: 117 fine chunks x 35 steps from gauge-corrected states; stores L,S. */
#define NCH1 39
#define BODY1 105
#define WARM 315
#define TS   35
#define NCH2 117
#define ROWW 44    /* smem row stride (floats): 176B, 16B-aligned for cp.async */

__device__ float g_flev  [NCH2][N_SERIES];
__device__ float g_fring [NCH2][SEAS][N_SERIES];
__device__ float g_endlev[NCH1][N_SERIES];
__device__ float g_gam   [NCH2][N_SERIES];

__device__ __forceinline__ float frcp(float x) {
    float r;
    asm("rcp.approx.f32 %0, %1;" : "=f"(r) : "f"(x));
    return r;
}

__device__ __forceinline__ uint32_t s2u(const void* p) {
    uint32_t a;
    asm("{ .reg .u64 t; cvta.to.shared.u64 t, %1; cvt.u32.u64 %0, t; }"
        : "=r"(a) : "l"(p));
    return a;
}
__device__ __forceinline__ void cp16(uint32_t d, const void* g) {
    asm volatile("cp.async.ca.shared.global [%0], [%1], 16;" :: "r"(d), "l"(g));
}
#define CP_COMMIT() asm volatile("cp.async.commit_group;" ::: "memory")
#define CP_WAIT0()  asm volatile("cp.async.wait_group 0;" ::: "memory")
#define CP_WAIT1()  asm volatile("cp.async.wait_group 1;" ::: "memory")

__device__ __forceinline__ void load_params(const int* idxs, const float* emb,
                                            int s, float& a, float& oma,
                                            float& b, float& omb, float* is)
{
    const float* ew = emb + (size_t)idxs[s] * EMB;
    a = 1.0f / (1.0f + __expf(-ew[0]));
    b = 1.0f / (1.0f + __expf(-ew[1]));
    oma = 1.0f - a;
    omb = 1.0f - b;
#pragma unroll
    for (int k = 0; k < SEAS; k++) is[k] = __expf(ew[2 + k]);
}

/* cooperative cp.async of a [32 series] x [40 floats] aligned window:
   320 16B chunks; item k = p*32+lane -> row r=k/10, chunk q=k%10.
   gmem: gsrc + (r<<12) + (q<<2)   (gsrc = series-group base + w0, w0%4==0)
   smem: sdst + (r*ROWW + q*4)*4.  'ovr' skips q==9 at the tensor edge. */
__device__ __forceinline__ void tile_cp(uint32_t sdst, const float* gsrc,
                                        int lane, bool ovr)
{
#pragma unroll
    for (int p = 0; p < 10; p++) {
        int k = p * 32 + lane;
        int r = k / 10;
        int q = k - r * 10;
        if (!(ovr && q == 9))
            cp16(sdst + (uint32_t)(r * ROWW + q * 4) * 4,
                 gsrc + (r << 12) + (q << 2));
    }
}

/* period-batched scan of one 35-step tile over the thread's own smem row.
   myrow points at the first step's y value (aligned-window offset folded in).
   When STORE: lev overwrites the consumed y slot; ns goes to tsrow. */
template<bool STORE>
__device__ __forceinline__ void scan_tile(float* myrow, float* tsrow,
                                          float a, float oma,
                                          float b, float omb,
                                          float& lev, float* ring, float* qring)
{
#pragma unroll
    for (int g = 0; g < TS / SEAS; g++) {
        float yt[SEAS], ax[SEAS];
#pragma unroll
        for (int j = 0; j < SEAS; j++) yt[j] = myrow[g * SEAS + j];
#pragma unroll
        for (int j = 0; j < SEAS; j++) ax[j] = a * (yt[j] * qring[j]);
#pragma unroll
        for (int j = 0; j < SEAS; j++) {
            lev = fmaf(oma, lev, ax[j]);
            if (STORE) myrow[g * SEAS + j] = lev;
            float ns = fmaf(omb, ring[j], (b * yt[j]) * frcp(lev));
            if (STORE) tsrow[g * SEAS + j] = ns;
            ring[j]  = ns;
            qring[j] = frcp(ns);
        }
    }
}

/* ---- Pass A: warmup+body per relay chunk, record fine states ---- */
__global__ void __launch_bounds__(32)
passA_kernel(const float* __restrict__ y, const int* __restrict__ idxs,
             const float* __restrict__ emb)
{
    __shared__ __align__(16) float ty[2][32][ROWW];
    const int c    = blockIdx.x / 64;
    const int sg   = blockIdx.x % 64;
    const int lane = threadIdx.x;
    const int s    = sg * 32 + lane;

    float a, oma, b, omb, is[SEAS];
    load_params(idxs, emb, s, a, oma, b, omb, is);

    const int tc = c * BODY1 + 1;
    int t0 = tc - WARM;
    if (t0 < 1) t0 = 1;
    const int wtiles = (tc - t0) / TS;
    const int ntiles = wtiles + 3;

    float lev = __fdividef(__ldg(y + (size_t)s * N_TIME + (t0 - 1)), is[0]);
    float ring[SEAS] = { is[1], is[2], is[3], is[4], is[5], is[6], is[0] };
    float qring[SEAS];
#pragma unroll
    for (int j = 0; j < SEAS; j++) qring[j] = frcp(ring[j]);

    const float* ygrp = y + (size_t)(sg * 32) * N_TIME;
    const uint32_t tyb0 = s2u(&ty[0][0][0]);
    const uint32_t tyb1 = s2u(&ty[1][0][0]);

    /* prefetch tile 0 */
    {
        int w0 = t0 & ~3;
        tile_cp(tyb0, ygrp + w0, lane, (w0 + 40 > N_TIME));
        CP_COMMIT();
    }

    int tstart = t0;
#pragma unroll 1
    for (int tile = 0; tile < ntiles; tile++) {
        const int buf = tile & 1;
        if (tile + 1 < ntiles) {
            int w0 = (tstart + TS) & ~3;
            tile_cp(buf ? tyb0 : tyb1, ygrp + w0, lane, (w0 + 40 > N_TIME));
            CP_COMMIT();
            CP_WAIT1();
        } else {
            CP_WAIT0();
        }
        __syncwarp();

        if (tile >= wtiles) {
            const int m = 3 * c + (tile - wtiles);
            g_flev[m][s] = lev;
#pragma unroll
            for (int j = 0; j < SEAS; j++) g_fring[m][j][s] = ring[j];
        }

        const int d = tstart & 3;
        float* myrow = &ty[buf][0][0] + lane * ROWW + d;
        scan_tile<false>(myrow, 0, a, oma, b, omb, lev, ring, qring);
        __syncwarp();
        tstart += TS;
    }
    g_endlev[c][s] = lev;
}

/* ---- gauge chain + per-fine-chunk gauge table ---- */
__global__ void fixup_kernel()
{
    int s = blockIdx.x * blockDim.x + threadIdx.x;
    if (s >= N_SERIES) return;
    float kap = 1.0f;
    for (int c = 0; c < NCH1; c++) {
        if (c >= 4)
            kap *= __fdividef(g_flev[3 * c][s], g_endlev[c - 1][s]);
        g_gam[3 * c][s]     = kap;
        g_gam[3 * c + 1][s] = kap;
        g_gam[3 * c + 2][s] = kap;
    }
}

/* ---- Pass C: 117 fine chunks x 35 steps, gauge-corrected, stores L,S ---- */
__global__ void __launch_bounds__(32)
passC_kernel(const float* __restrict__ y, const int* __restrict__ idxs,
             const float* __restrict__ emb,
             float* __restrict__ L, float* __restrict__ S)
{
    __shared__ __align__(16) float ty[32][ROWW];   /* y tile -> L tile */
    __shared__ float ts[32][37];
    const int m    = blockIdx.x / 64;
    const int sg   = blockIdx.x % 64;
    const int lane = threadIdx.x;
    const int s    = sg * 32 + lane;

    const int tstart = m * TS + 1;
    const int d  = tstart & 3;
    const int w0 = tstart - d;

    const float* ygrp = y + (size_t)(sg * 32) * N_TIME;
    tile_cp(s2u(&ty[0][0]), ygrp + w0, lane, (w0 + 40 > N_TIME));
    CP_COMMIT();

    float a, oma, b, omb, is[SEAS];
    load_params(idxs, emb, s, a, oma, b, omb, is);

    const float gam  = g_gam[m][s];
    const float igam = frcp(gam);
    float lev = g_flev[m][s] * igam;
    float ring[SEAS], qring[SEAS];
#pragma unroll
    for (int j = 0; j < SEAS; j++) {
        ring[j]  = g_fring[m][j][s] * gam;
        qring[j] = frcp(ring[j]);
    }

    if (m == 0) {
        float* Sr = S + (size_t)s * S_LEN;
#pragma unroll
        for (int k = 0; k < SEAS; k++) Sr[k] = is[k];
        Sr[SEAS] = is[0];
        L[(size_t)s * N_TIME] = lev;
    }

    CP_WAIT0();
    __syncwarp();

    float* myrow = &ty[0][0] + lane * ROWW + d;
    float* tsrow = &ts[0][0] + lane * 37;
    scan_tile<true>(myrow, tsrow, a, oma, b, omb, lev, ring, qring);
    __syncwarp();

    /* coalesced flush: thread = time offset */
    {
        float* Lp = L + (size_t)(sg * 32) * N_TIME + tstart + lane;
        float* Sp = S + (size_t)(sg * 32) * S_LEN + tstart + SEAS + lane;
        const float* typ = &ty[0][0] + d + lane;
        const float* tsp = &ts[0][0] + lane;
#pragma unroll 8
        for (int r = 0; r < 32; r++) {
            Lp[0] = typ[0];
            Sp[0] = tsp[0];
            if (lane < 3) {
                Lp[32] = typ[32];
                Sp[32] = tsp[32];
            }
            Lp += N_TIME; Sp += S_LEN; typ += ROWW; tsp += 37;
        }
    }
}

__global__ void windows_kernel(const float* __restrict__ y,
                               const float* __restrict__ L,
                               const float* __restrict__ S,
                               float* __restrict__ yhat,
                               float* __restrict__ ywin)
{
    const int NH = OUTPUT_SIZE * N_SERIES * INPUT_SIZE;   /* 401408 */
    const int NZ = OUTPUT_SIZE * N_SERIES * OUTPUT_SIZE;  /* 100352 */
    int i = blockIdx.x * blockDim.x + threadIdx.x;
    if (i < NH) {
        int ii   = i % INPUT_SIZE;
        int rest = i / INPUT_SIZE;
        int s    = rest % N_SERIES;
        int w    = rest / N_SERIES;
        int start = N_TIME - INPUT_SIZE - OUTPUT_SIZE + 1 + w;
        int t = start + ii;
        float lev = L[(size_t)s * N_TIME + (start + INPUT_SIZE - 1)];
        float se  = S[(size_t)s * S_LEN  + t];
        float yy  = y[(size_t)s * N_TIME + t];
        yhat[i] = logf(yy / (lev * se));
    } else if (i < NH + NZ) {
        ywin[i - NH] = 0.0f;
    }
}

extern "C" void kernel_launch(void* const* d_in, const int* in_sizes, int n_in,
                              void* d_out, int out_size) {
    const float* y    = (const float*)d_in[0];
    const int*   idxs = (const int*)  d_in[1];
    const float* emb  = (const float*)d_in[2];

    float* out  = (float*)d_out;
    float* yhat = out + OFF_YHAT;
    float* ywin = out + OFF_YWIN;
    float* L    = out + OFF_LEV;
    float* S    = out + OFF_SEAS;

    passA_kernel<<<NCH1 * 64, 32>>>(y, idxs, emb);
    fixup_kernel<<<(N_SERIES + 255) / 256, 256>>>();
    passC_kernel<<<NCH2 * 64, 32>>>(y, idxs, emb, L, S);

    const int tot = OUTPUT_SIZE * N_SERIES * (INPUT_SIZE + OUTPUT_SIZE); /* 501760 */
    windows_kernel<<<(tot + 255) / 256, 256>>>(y, L, S, yhat, ywin);
}